// round 9
// baseline (speedup 1.0000x reference)
#include <cuda_runtime.h>
#include <cuda_bf16.h>
#include <math.h>
#include <stdint.h>

// Problem constants
#define Bq   4
#define Nq   1024
#define Dq   1024
#define Hh   8
#define Lr   512
#define DKq  128

#define INV_SCALE 0.051031036307982884f  // 1/sqrt(128*3)

// ======================= portable PTX helpers ===============================
__device__ __forceinline__ uint32_t smem_to_u32(const void* p) {
    uint32_t a;
    asm("{ .reg .u64 t; cvta.to.shared.u64 t, %1; cvt.u32.u64 %0, t; }" : "=r"(a) : "l"(p));
    return a;
}
#define CP_ASYNC_16(dst_u32, src_ptr) \
    asm volatile("cp.async.cg.shared.global [%0], [%1], 16;" :: "r"(dst_u32), "l"(src_ptr))
#define CP_ASYNC_COMMIT() asm volatile("cp.async.commit_group;" ::: "memory")
#define CP_ASYNC_WAIT(n)  asm volatile("cp.async.wait_group %0;" :: "n"(n) : "memory")

// m16n8k16 bf16 MMA, fp32 accum (portable sm_80+ PTX -> HMMA on Blackwell)
__device__ __forceinline__ void mma16816(float* c, const uint32_t* a, const uint32_t* b) {
    asm volatile(
        "mma.sync.aligned.m16n8k16.row.col.f32.bf16.bf16.f32 "
        "{%0,%1,%2,%3}, {%4,%5,%6,%7}, {%8,%9}, {%0,%1,%2,%3};"
        : "+f"(c[0]), "+f"(c[1]), "+f"(c[2]), "+f"(c[3])
        : "r"(a[0]), "r"(a[1]), "r"(a[2]), "r"(a[3]), "r"(b[0]), "r"(b[1]));
}

__device__ __forceinline__ void split1(float x, __nv_bfloat16& h, __nv_bfloat16& l) {
    h = __float2bfloat16(x);
    l = __float2bfloat16(x - __bfloat162float(h));
}

// ================== scratch (device globals; no allocs) =====================
__device__ float g_v  [Bq*Nq*Dq];
__device__ float g_Llq[Lr*512];
__device__ float g_Ltq[Lr*512];
__device__ float g_Llk[Lr*512];
__device__ float g_Ltk[Lr*512];
__device__ float g_lqp[Hh*Lr*DKq];
__device__ float g_lkp[Hh*Lr*DKq];
__device__ float g_c2p [(size_t)Bq*Hh*Nq*Lr];
__device__ float g_p2cT[(size_t)Bq*Hh*Nq*Lr];
__device__ float g_S   [(size_t)Bq*Hh*Nq*Nq];    // c2c scores (pre-scaled)

#define NELT (Bq*Nq*Dq)
// bf16 hi/lo splits
__device__ __nv_bfloat16 s_qry_h[NELT], s_qry_l[NELT];
__device__ __nv_bfloat16 s_key_h[NELT], s_key_l[NELT];
__device__ __nv_bfloat16 s_val_h[NELT], s_val_l[NELT];
__device__ __nv_bfloat16 s_pq_h [NELT], s_pq_l [NELT];   // projected q (from GEMM epilogue)
__device__ __nv_bfloat16 s_pk_h [NELT], s_pk_l [NELT];   // projected k
__device__ __nv_bfloat16 s_att_h[NELT], s_att_l[NELT];   // attn out (from attn epilogue)
__device__ __nv_bfloat16 wtq_h[Dq*Dq], wtq_l[Dq*Dq];     // W^T [N][K]
__device__ __nv_bfloat16 wtk_h[Dq*Dq], wtk_l[Dq*Dq];
__device__ __nv_bfloat16 wtv_h[Dq*Dq], wtv_l[Dq*Dq];
__device__ __nv_bfloat16 wto_h[Dq*Dq], wto_l[Dq*Dq];
__device__ __nv_bfloat16 wtlq_h[512*Dq], wtlq_l[512*Dq];
__device__ __nv_bfloat16 wtlk_h[512*Dq], wtlk_l[512*Dq];
__device__ __nv_bfloat16 wttq_h[512*Dq], wttq_l[512*Dq];
__device__ __nv_bfloat16 wttk_h[512*Dq], wttk_l[512*Dq];
__device__ __nv_bfloat16 s_l_h[Lr*Dq], s_l_l[Lr*Dq];
__device__ __nv_bfloat16 s_t_h[Lr*Dq], s_t_l[Lr*Dq];
__device__ __nv_bfloat16 s_lqp_h[Hh*Lr*DKq], s_lqp_l[Hh*Lr*DKq];
__device__ __nv_bfloat16 s_lkp_h[Hh*Lr*DKq], s_lkp_l[Hh*Lr*DKq];

// ==================== elementwise fp32 -> bf16 hi/lo ========================
__global__ void split_f32(const float* __restrict__ src,
                          __nv_bfloat16* __restrict__ hi, __nv_bfloat16* __restrict__ lo)
{
    int i = (blockIdx.x * blockDim.x + threadIdx.x) * 4;
    float4 v = *(const float4*)(src + i);
    float x[4] = {v.x, v.y, v.z, v.w};
    __nv_bfloat16 h[4], l[4];
    #pragma unroll
    for (int t = 0; t < 4; t++) split1(x[t], h[t], l[t]);
    *(__nv_bfloat162*)(hi + i)     = __nv_bfloat162(h[0], h[1]);
    *(__nv_bfloat162*)(hi + i + 2) = __nv_bfloat162(h[2], h[3]);
    *(__nv_bfloat162*)(lo + i)     = __nv_bfloat162(l[0], l[1]);
    *(__nv_bfloat162*)(lo + i + 2) = __nv_bfloat162(l[2], l[3]);
}

// ============ transpose + split: W[K,N] fp32 -> Wt_hi/lo [N,K] bf16 =========
__global__ void tsplit(const float* __restrict__ W, int Kd, int Nd,
                       __nv_bfloat16* __restrict__ Th, __nv_bfloat16* __restrict__ Tl)
{
    __shared__ float t[32][33];
    int k0 = blockIdx.x * 32, n0 = blockIdx.y * 32;
    int tx = threadIdx.x, ty = threadIdx.y;            // 32 x 8
    for (int r = ty; r < 32; r += 8)
        t[r][tx] = W[(size_t)(k0 + r) * Nd + n0 + tx];
    __syncthreads();
    for (int r = ty; r < 32; r += 8) {
        float x = t[tx][r];                            // W[k0+tx][n0+r]
        __nv_bfloat16 h, l;
        split1(x, h, l);
        Th[(size_t)(n0 + r) * Kd + k0 + tx] = h;
        Tl[(size_t)(n0 + r) * Kd + k0 + tx] = l;
    }
}

// ============== warp-MMA bf16x3 GEMM: C = alpha*(A @ B^T) + bias ============
// A [M,K] (hi/lo, K-major, lda), B [N,K] (hi/lo, K-major, ldb), C [M,N] fp32.
// CTA tile 128x128, 8 warps x (64x32), m16n8k16, K-chunk 32, double-buffered
// cp.async. mode 0: plain. mode 1: A batched z=(b,h), B over h. mode 2: both.
// Optional Chi/Clo (mode 0 only): bf16 hi/lo split of the result, same layout.
#define KC    32
#define SROW  40                      // padded row length (bf16) -> 80B stride
#define ABYT  (128 * SROW * 2)        // 10240 bytes per sub-array
#define STG   (4 * ABYT)              // 40960 per stage

__global__ __launch_bounds__(256)
void gemm_tc(const __nv_bfloat16* __restrict__ Ah_, const __nv_bfloat16* __restrict__ Al_,
             int lda, size_t aBatch,
             const __nv_bfloat16* __restrict__ Bh_, const __nv_bfloat16* __restrict__ Bl_,
             int ldb, size_t bBatch,
             float* __restrict__ C_, int ldc, size_t cBatch,
             __nv_bfloat16* __restrict__ Chi, __nv_bfloat16* __restrict__ Clo,
             const float* __restrict__ bias, float alpha, int K, int mode)
{
    extern __shared__ char dynsm[];
    const uint32_t smem_u = smem_to_u32(dynsm);
    const int tid = threadIdx.x;
    const int w = tid >> 5, lane = tid & 31;
    const int g = lane >> 2, tg = lane & 3;
    const int wm = w & 1, wn = w >> 1;                 // warp tile: 64x32

    const __nv_bfloat16 *Ah = Ah_, *Al = Al_, *Bh = Bh_, *Bl = Bl_;
    float* C = C_;
    if (mode) {
        int z = blockIdx.z, b = z >> 3, h = z & 7;
        size_t ao = (size_t)b * aBatch + (size_t)h * 128;
        Ah += ao; Al += ao;
        if (mode == 1) { Bh += (size_t)h * bBatch; Bl += (size_t)h * bBatch; }
        else           { Bh += ao; Bl += ao; }
        C += (size_t)z * cBatch;
    }
    const int m0 = blockIdx.x * 128, n0 = blockIdx.y * 128;

    float acc[4][4][4] = {};                           // [mi][ni][c0..c3]

    const int nchunks = K / KC;

    // per-thread load slice: 2048 16B-copies per chunk, 8 per thread
    // it = tid + 256*u; arr = it>>9 (AH,AL,BH,BL), idx = it&511: row=idx>>2, seg=idx&3
    auto load_chunk = [&](int kc, int st) {
        const int k0 = kc * KC;
        uint32_t stbase = smem_u + st * STG;
        #pragma unroll
        for (int u = 0; u < 8; u++) {
            int it = tid + 256 * u;
            int arr = it >> 9, idx = it & 511;
            int row = idx >> 2, seg = idx & 3;
            uint32_t so = stbase + arr * ABYT + row * (SROW * 2) + seg * 16;
            const __nv_bfloat16* gp;
            if (arr == 0)      gp = Ah + (size_t)(m0 + row) * lda + k0 + seg * 8;
            else if (arr == 1) gp = Al + (size_t)(m0 + row) * lda + k0 + seg * 8;
            else if (arr == 2) gp = Bh + (size_t)(n0 + row) * ldb + k0 + seg * 8;
            else               gp = Bl + (size_t)(n0 + row) * ldb + k0 + seg * 8;
            CP_ASYNC_16(so, gp);
        }
        CP_ASYNC_COMMIT();
    };

    load_chunk(0, 0);
    for (int kc = 0; kc < nchunks; kc++) {
        const int st = kc & 1;
        bool more = (kc + 1 < nchunks);
        if (more) load_chunk(kc + 1, st ^ 1);
        if (more) { CP_ASYNC_WAIT(1); } else { CP_ASYNC_WAIT(0); }
        __syncthreads();

        const char* sbase = dynsm + st * STG;
        const char* pAh = sbase;
        const char* pAl = sbase + ABYT;
        const char* pBh = sbase + 2 * ABYT;
        const char* pBl = sbase + 3 * ABYT;

        #pragma unroll
        for (int ks = 0; ks < KC / 16; ks++) {
            const int kb = ks * 16 * 2;                // byte offset of k0 in a row
            uint32_t fAh[4][4], fAl[4][4], fBh[4][2], fBl[4][2];
            #pragma unroll
            for (int mi = 0; mi < 4; mi++) {
                int r0 = (wm * 64 + mi * 16 + g) * (SROW * 2) + kb + tg * 4;
                int r1 = r0 + 8 * (SROW * 2);
                fAh[mi][0] = *(const uint32_t*)(pAh + r0);
                fAh[mi][1] = *(const uint32_t*)(pAh + r1);
                fAh[mi][2] = *(const uint32_t*)(pAh + r0 + 16);
                fAh[mi][3] = *(const uint32_t*)(pAh + r1 + 16);
                fAl[mi][0] = *(const uint32_t*)(pAl + r0);
                fAl[mi][1] = *(const uint32_t*)(pAl + r1);
                fAl[mi][2] = *(const uint32_t*)(pAl + r0 + 16);
                fAl[mi][3] = *(const uint32_t*)(pAl + r1 + 16);
            }
            #pragma unroll
            for (int ni = 0; ni < 4; ni++) {
                int r0 = (wn * 32 + ni * 8 + g) * (SROW * 2) + kb + tg * 4;
                fBh[ni][0] = *(const uint32_t*)(pBh + r0);
                fBh[ni][1] = *(const uint32_t*)(pBh + r0 + 16);
                fBl[ni][0] = *(const uint32_t*)(pBl + r0);
                fBl[ni][1] = *(const uint32_t*)(pBl + r0 + 16);
            }
            #pragma unroll
            for (int mi = 0; mi < 4; mi++)
                #pragma unroll
                for (int ni = 0; ni < 4; ni++) {
                    mma16816(acc[mi][ni], fAh[mi], fBh[ni]);
                    mma16816(acc[mi][ni], fAh[mi], fBl[ni]);
                    mma16816(acc[mi][ni], fAl[mi], fBh[ni]);
                }
        }
        __syncthreads();
    }

    // epilogue
    #pragma unroll
    for (int mi = 0; mi < 4; mi++) {
        int row0 = m0 + wm * 64 + mi * 16 + g;
        #pragma unroll
        for (int ni = 0; ni < 4; ni++) {
            int col = n0 + wn * 32 + ni * 8 + tg * 2;
            float b0 = bias ? bias[col] : 0.f;
            float b1 = bias ? bias[col + 1] : 0.f;
            float v00 = acc[mi][ni][0] * alpha + b0, v01 = acc[mi][ni][1] * alpha + b1;
            float v10 = acc[mi][ni][2] * alpha + b0, v11 = acc[mi][ni][3] * alpha + b1;
            if (C) {
                *(float2*)(C + (size_t)row0 * ldc + col)       = make_float2(v00, v01);
                *(float2*)(C + (size_t)(row0 + 8) * ldc + col) = make_float2(v10, v11);
            }
            if (Chi) {
                __nv_bfloat16 h00, l00, h01, l01, h10, l10, h11, l11;
                split1(v00, h00, l00); split1(v01, h01, l01);
                split1(v10, h10, l10); split1(v11, h11, l11);
                *(__nv_bfloat162*)(Chi + (size_t)row0 * ldc + col)       = __nv_bfloat162(h00, h01);
                *(__nv_bfloat162*)(Chi + (size_t)(row0 + 8) * ldc + col) = __nv_bfloat162(h10, h11);
                *(__nv_bfloat162*)(Clo + (size_t)row0 * ldc + col)       = __nv_bfloat162(l00, l01);
                *(__nv_bfloat162*)(Clo + (size_t)(row0 + 8) * ldc + col) = __nv_bfloat162(l10, l11);
            }
        }
    }
}

// ---- pack concat heads: out[h][r][d] = (h<4 ? Ll : Lt)[r][ (h%4)*128 + d ] --
__global__ void pack_rel(const float* __restrict__ Ll, const float* __restrict__ Lt,
                         float* __restrict__ out)
{
    int idx = blockIdx.x * blockDim.x + threadIdx.x;
    int d = idx & 127;
    int r = (idx >> 7) & 511;
    int h = idx >> 16;
    const float* src = (h < 4) ? Ll : Lt;
    out[idx] = src[r * 512 + (h & 3) * 128 + d];
}

// ------------- fused gathers + mask + softmax + AV (c2c precomputed) --------
// CTA = (b,h) x 32 query rows; 8 warps, each warp 4 rows; lane = j within tile.
// Output written directly as bf16 hi/lo split (consumed by the Wo GEMM).
__global__ __launch_bounds__(256, 2)
void attn_fused(const int* __restrict__ rel, const int* __restrict__ mask)
{
    extern __shared__ char dynsm[];
    float* c2ps = (float*)dynsm;          // [32][512]
    float* vs   = c2ps + 32 * 512;        // [32][128]

    const int bh = blockIdx.y;
    const int b = bh >> 3, h = bh & 7;
    const int i0 = blockIdx.x * 32;
    const int tid = threadIdx.x;
    const int w  = tid >> 5;
    const int jj = tid & 31;
    const int r0 = w * 4;

    for (int e = tid * 4; e < 32 * 512; e += 1024)
        *(float4*)&c2ps[e] =
            *(const float4*)(g_c2p + ((size_t)bh * Nq + i0 + (e >> 9)) * Lr + (e & 511));

    float m[4] = {-INFINITY, -INFINITY, -INFINITY, -INFINITY};
    float l[4] = {0.f, 0.f, 0.f, 0.f};
    float4 acc[4] = {};

    const float* Sb   = g_S + (size_t)bh * Nq * Nq;
    const int* relbh  = rel + (size_t)bh * Nq * Nq;
    const int* maskb  = mask + (size_t)b * Nq * Nq;
    const float* p2cb = g_p2cT + (size_t)bh * Nq * Lr;

    for (int j0 = 0; j0 < Nq; j0 += 32) {
        __syncthreads();
        #pragma unroll
        for (int t = 0; t < 4; t++) {
            int e = (tid + t * 256) * 4;
            int r = e >> 7, d = e & 127;
            *(float4*)&vs[e] =
                *(const float4*)(g_v + (size_t)(b * Nq + j0 + r) * Dq + h * DKq + d);
        }
        __syncthreads();

        const int j = j0 + jj;
        int4 r2v = *(const int4*)(relbh + (size_t)j * Nq + i0 + r0);
        const int* r2a = (const int*)&r2v;
        float s[4];
        #pragma unroll
        for (int r = 0; r < 4; r++) {
            int i = i0 + r0 + r;
            float sc = __ldg(Sb + (size_t)i * Nq + j);
            int r1 = __ldg(relbh + (size_t)i * Nq + j);
            sc += c2ps[(r0 + r) * 512 + r1];
            sc += __ldg(p2cb + (size_t)j * Lr + r2a[r]);
            if (__ldg(maskb + (size_t)i * Nq + j) == 1) sc = -1e9f;
            s[r] = sc;
        }
        float p[4];
        #pragma unroll
        for (int r = 0; r < 4; r++) {
            float t = s[r];
            #pragma unroll
            for (int o = 16; o; o >>= 1) t = fmaxf(t, __shfl_xor_sync(0xffffffffu, t, o));
            float mn = fmaxf(m[r], t);
            p[r] = __expf(s[r] - mn);
            float corr = __expf(m[r] - mn);
            float ps = p[r];
            #pragma unroll
            for (int o = 16; o; o >>= 1) ps += __shfl_xor_sync(0xffffffffu, ps, o);
            l[r] = l[r] * corr + ps;
            m[r] = mn;
            acc[r].x *= corr; acc[r].y *= corr; acc[r].z *= corr; acc[r].w *= corr;
        }
        #pragma unroll
        for (int t2 = 0; t2 < 32; t2++) {
            float4 vr = *(float4*)&vs[t2 * 128 + jj * 4];
            #pragma unroll
            for (int r = 0; r < 4; r++) {
                float pj = __shfl_sync(0xffffffffu, p[r], t2);
                acc[r].x += pj * vr.x; acc[r].y += pj * vr.y;
                acc[r].z += pj * vr.z; acc[r].w += pj * vr.w;
            }
        }
    }
    #pragma unroll
    for (int r = 0; r < 4; r++) {
        float inv = 1.f / l[r];
        float o[4] = {acc[r].x * inv, acc[r].y * inv, acc[r].z * inv, acc[r].w * inv};
        __nv_bfloat16 hh[4], ll[4];
        #pragma unroll
        for (int t = 0; t < 4; t++) split1(o[t], hh[t], ll[t]);
        size_t base = ((size_t)(b * Nq + i0 + r0 + r) * Hh + h) * DKq + jj * 4;
        *(__nv_bfloat162*)(s_att_h + base)     = __nv_bfloat162(hh[0], hh[1]);
        *(__nv_bfloat162*)(s_att_h + base + 2) = __nv_bfloat162(hh[2], hh[3]);
        *(__nv_bfloat162*)(s_att_l + base)     = __nv_bfloat162(ll[0], ll[1]);
        *(__nv_bfloat162*)(s_att_l + base + 2) = __nv_bfloat162(ll[2], ll[3]);
    }
}

// ---------------------------------------------------------------------------
#define GSA(p, sym) cudaGetSymbolAddress((void**)&p, sym)

extern "C" void kernel_launch(void* const* d_in, const int* in_sizes, int n_in,
                              void* d_out, int out_size)
{
    const float* query   = (const float*)d_in[0];
    const float* key     = (const float*)d_in[1];
    const float* value   = (const float*)d_in[2];
    const float* rel_emb = (const float*)d_in[3];
    const int*   rel     = (const int*)  d_in[4];
    const int*   mask    = (const int*)  d_in[5];
    const float* Wq  = (const float*)d_in[6];  const float* bq  = (const float*)d_in[7];
    const float* Wk  = (const float*)d_in[8];  const float* bk  = (const float*)d_in[9];
    const float* Wv  = (const float*)d_in[10]; const float* bv  = (const float*)d_in[11];
    const float* Wo  = (const float*)d_in[12]; const float* bo  = (const float*)d_in[13];
    const float* Wlq = (const float*)d_in[14]; const float* blq = (const float*)d_in[15];
    const float* Wlk = (const float*)d_in[16]; const float* blk = (const float*)d_in[17];
    const float* Wtq = (const float*)d_in[18]; const float* btq = (const float*)d_in[19];
    const float* Wtk = (const float*)d_in[20]; const float* btk = (const float*)d_in[21];
    float* out = (float*)d_out;

    float *p_v, *p_Llq, *p_Ltq, *p_Llk, *p_Ltk, *p_lqp, *p_lkp;
    float *p_c2p, *p_p2cT, *p_S;
    GSA(p_v, g_v);
    GSA(p_Llq, g_Llq); GSA(p_Ltq, g_Ltq); GSA(p_Llk, g_Llk); GSA(p_Ltk, g_Ltk);
    GSA(p_lqp, g_lqp); GSA(p_lkp, g_lkp); GSA(p_c2p, g_c2p); GSA(p_p2cT, g_p2cT);
    GSA(p_S, g_S);

    __nv_bfloat16 *qry_h,*qry_l,*key_h,*key_l,*val_h,*val_l,*pq_h,*pq_l,*pk_h,*pk_l,*att_h,*att_l;
    __nv_bfloat16 *wq_h,*wq_l,*wk_h,*wk_l,*wv_h,*wv_l,*wo_h,*wo_l;
    __nv_bfloat16 *wlq_h,*wlq_l,*wlk_h,*wlk_l,*wtq_hh,*wtq_ll,*wtk_hh,*wtk_ll;
    __nv_bfloat16 *l_h,*l_l,*t_h,*t_l,*lqp_h,*lqp_l,*lkp_h,*lkp_l;
    GSA(qry_h, s_qry_h); GSA(qry_l, s_qry_l);
    GSA(key_h, s_key_h); GSA(key_l, s_key_l);
    GSA(val_h, s_val_h); GSA(val_l, s_val_l);
    GSA(pq_h, s_pq_h); GSA(pq_l, s_pq_l);
    GSA(pk_h, s_pk_h); GSA(pk_l, s_pk_l);
    GSA(att_h, s_att_h); GSA(att_l, s_att_l);
    GSA(wq_h, wtq_h); GSA(wq_l, wtq_l); GSA(wk_h, wtk_h); GSA(wk_l, wtk_l);
    GSA(wv_h, wtv_h); GSA(wv_l, wtv_l); GSA(wo_h, wto_h); GSA(wo_l, wto_l);
    GSA(wlq_h, wtlq_h); GSA(wlq_l, wtlq_l); GSA(wlk_h, wtlk_h); GSA(wlk_l, wtlk_l);
    GSA(wtq_hh, wttq_h); GSA(wtq_ll, wttq_l); GSA(wtk_hh, wttk_h); GSA(wtk_ll, wttk_l);
    GSA(l_h, s_l_h); GSA(l_l, s_l_l); GSA(t_h, s_t_h); GSA(t_l, s_t_l);
    GSA(lqp_h, s_lqp_h); GSA(lqp_l, s_lqp_l); GSA(lkp_h, s_lkp_h); GSA(lkp_l, s_lkp_l);

    const float* lmat = rel_emb;
    const float* tmat = rel_emb + Lr * Dq;

    const int GEMM_SMEM = 2 * STG;                          // 81920 B
    cudaFuncSetAttribute(gemm_tc, cudaFuncAttributeMaxDynamicSharedMemorySize, GEMM_SMEM);
    const int ATTN_SMEM = (32 * 512 + 32 * 128) * 4;        // 80 KB
    cudaFuncSetAttribute(attn_fused, cudaFuncAttributeMaxDynamicSharedMemorySize, ATTN_SMEM);

    // 0) weight transpose+split; activation splits
    {
        dim3 t32(32, 8);
        tsplit<<<dim3(32, 32), t32>>>(Wq, Dq, Dq, wq_h, wq_l);
        tsplit<<<dim3(32, 32), t32>>>(Wk, Dq, Dq, wk_h, wk_l);
        tsplit<<<dim3(32, 32), t32>>>(Wv, Dq, Dq, wv_h, wv_l);
        tsplit<<<dim3(32, 32), t32>>>(Wo, Dq, Dq, wo_h, wo_l);
        tsplit<<<dim3(32, 16), t32>>>(Wlq, Dq, 512, wlq_h, wlq_l);
        tsplit<<<dim3(32, 16), t32>>>(Wlk, Dq, 512, wlk_h, wlk_l);
        tsplit<<<dim3(32, 16), t32>>>(Wtq, Dq, 512, wtq_hh, wtq_ll);
        tsplit<<<dim3(32, 16), t32>>>(Wtk, Dq, 512, wtk_hh, wtk_ll);
        split_f32<<<NELT / 1024, 256>>>(query, qry_h, qry_l);
        split_f32<<<NELT / 1024, 256>>>(key,   key_h, key_l);
        split_f32<<<NELT / 1024, 256>>>(value, val_h, val_l);
        split_f32<<<(Lr * Dq) / 1024, 256>>>(lmat, l_h, l_l);
        split_f32<<<(Lr * Dq) / 1024, 256>>>(tmat, t_h, t_l);
    }

    // 1) q/k/v projections  [4096,1024]@[1024,1024]+b
    //    q/k: write bf16 hi/lo splits directly (fp32 never materialized)
    gemm_tc<<<dim3(32, 8, 1), 256, GEMM_SMEM>>>(qry_h, qry_l, Dq, 0, wq_h, wq_l, Dq, 0,
                                                nullptr, Dq, 0, pq_h, pq_l, bq, 1.f, Dq, 0);
    gemm_tc<<<dim3(32, 8, 1), 256, GEMM_SMEM>>>(key_h, key_l, Dq, 0, wk_h, wk_l, Dq, 0,
                                                nullptr, Dq, 0, pk_h, pk_l, bk, 1.f, Dq, 0);
    gemm_tc<<<dim3(32, 8, 1), 256, GEMM_SMEM>>>(val_h, val_l, Dq, 0, wv_h, wv_l, Dq, 0,
                                                p_v, Dq, 0, nullptr, nullptr, bv, 1.f, Dq, 0);

    // 2) rel projections [512,1024]@[1024,512]+b
    gemm_tc<<<dim3(4, 4, 1), 256, GEMM_SMEM>>>(l_h, l_l, Dq, 0, wlq_h, wlq_l, Dq, 0,
                                               p_Llq, 512, 0, nullptr, nullptr, blq, 1.f, Dq, 0);
    gemm_tc<<<dim3(4, 4, 1), 256, GEMM_SMEM>>>(l_h, l_l, Dq, 0, wlk_h, wlk_l, Dq, 0,
                                               p_Llk, 512, 0, nullptr, nullptr, blk, 1.f, Dq, 0);
    gemm_tc<<<dim3(4, 4, 1), 256, GEMM_SMEM>>>(t_h, t_l, Dq, 0, wtq_hh, wtq_ll, Dq, 0,
                                               p_Ltq, 512, 0, nullptr, nullptr, btq, 1.f, Dq, 0);
    gemm_tc<<<dim3(4, 4, 1), 256, GEMM_SMEM>>>(t_h, t_l, Dq, 0, wtk_hh, wtk_ll, Dq, 0,
                                               p_Ltk, 512, 0, nullptr, nullptr, btk, 1.f, Dq, 0);

    // 3) pack + splits (rel tables only)
    pack_rel<<<(Hh * Lr * DKq) / 256, 256>>>(p_Llq, p_Ltq, p_lqp);
    pack_rel<<<(Hh * Lr * DKq) / 256, 256>>>(p_Llk, p_Ltk, p_lkp);
    split_f32<<<(Hh * Lr * DKq) / 1024, 256>>>(p_lqp, lqp_h, lqp_l);
    split_f32<<<(Hh * Lr * DKq) / 1024, 256>>>(p_lkp, lkp_h, lkp_l);

    // 4) c2p_full[b,h,i,r]=(q_i.lk_r)/scale ; p2cT[b,h,j,r]=(k_j.lq_r)/scale
    gemm_tc<<<dim3(8, 4, 32), 256, GEMM_SMEM>>>(pq_h, pq_l, Dq, (size_t)Nq * Dq,
                                                lkp_h, lkp_l, DKq, (size_t)Lr * DKq,
                                                p_c2p, Lr, (size_t)Nq * Lr,
                                                nullptr, nullptr, nullptr, INV_SCALE, DKq, 1);
    gemm_tc<<<dim3(8, 4, 32), 256, GEMM_SMEM>>>(pk_h, pk_l, Dq, (size_t)Nq * Dq,
                                                lqp_h, lqp_l, DKq, (size_t)Lr * DKq,
                                                p_p2cT, Lr, (size_t)Nq * Lr,
                                                nullptr, nullptr, nullptr, INV_SCALE, DKq, 1);

    // 5) c2c scores: S[b,h,i,j] = (q_i.k_j)/scale   (batched over (b,h))
    gemm_tc<<<dim3(8, 8, 32), 256, GEMM_SMEM>>>(pq_h, pq_l, Dq, (size_t)Nq * Dq,
                                                pk_h, pk_l, Dq, 0,
                                                p_S, Nq, (size_t)Nq * Nq,
                                                nullptr, nullptr, nullptr, INV_SCALE, DKq, 2);

    // 6) fused attention (gathers + softmax + AV) -> writes att hi/lo splits
    attn_fused<<<dim3(Nq / 32, Bq * Hh), 256, ATTN_SMEM>>>(rel, mask);

    // 7) output projection
    gemm_tc<<<dim3(32, 8, 1), 256, GEMM_SMEM>>>(att_h, att_l, Dq, 0, wo_h, wo_l, Dq, 0,
                                                out, Dq, 0, nullptr, nullptr, bo, 1.f, Dq, 0);
}

// round 10
// speedup vs baseline: 1.0830x; 1.0830x over previous
#include <cuda_runtime.h>
#include <cuda_bf16.h>
#include <math.h>
#include <stdint.h>

// Problem constants
#define Bq   4
#define Nq   1024
#define Dq   1024
#define Hh   8
#define Lr   512
#define DKq  128

#define INV_SCALE 0.051031036307982884f  // 1/sqrt(128*3)

// ======================= portable PTX helpers ===============================
__device__ __forceinline__ uint32_t smem_to_u32(const void* p) {
    uint32_t a;
    asm("{ .reg .u64 t; cvta.to.shared.u64 t, %1; cvt.u32.u64 %0, t; }" : "=r"(a) : "l"(p));
    return a;
}
#define CP_ASYNC_16(dst_u32, src_ptr) \
    asm volatile("cp.async.cg.shared.global [%0], [%1], 16;" :: "r"(dst_u32), "l"(src_ptr))
#define CP_ASYNC_COMMIT() asm volatile("cp.async.commit_group;" ::: "memory")
#define CP_ASYNC_WAIT(n)  asm volatile("cp.async.wait_group %0;" :: "n"(n) : "memory")

// m16n8k16 bf16 MMA, fp32 accum (portable sm_80+ PTX -> HMMA on Blackwell)
__device__ __forceinline__ void mma16816(float* c, const uint32_t* a, const uint32_t* b) {
    asm volatile(
        "mma.sync.aligned.m16n8k16.row.col.f32.bf16.bf16.f32 "
        "{%0,%1,%2,%3}, {%4,%5,%6,%7}, {%8,%9}, {%0,%1,%2,%3};"
        : "+f"(c[0]), "+f"(c[1]), "+f"(c[2]), "+f"(c[3])
        : "r"(a[0]), "r"(a[1]), "r"(a[2]), "r"(a[3]), "r"(b[0]), "r"(b[1]));
}

// ldmatrix x4: loads 4 8x8 b16 matrices; lane i of each 8-lane group supplies a row addr
__device__ __forceinline__ void ldsm4(uint32_t* r, uint32_t a) {
    asm volatile("ldmatrix.sync.aligned.m8n8.x4.shared.b16 {%0,%1,%2,%3}, [%4];"
        : "=r"(r[0]), "=r"(r[1]), "=r"(r[2]), "=r"(r[3]) : "r"(a));
}

__device__ __forceinline__ void split1(float x, __nv_bfloat16& h, __nv_bfloat16& l) {
    h = __float2bfloat16(x);
    l = __float2bfloat16(x - __bfloat162float(h));
}

// ================== scratch (device globals; no allocs) =====================
__device__ float g_v  [Bq*Nq*Dq];
__device__ float g_Llq[Lr*512];
__device__ float g_Ltq[Lr*512];
__device__ float g_Llk[Lr*512];
__device__ float g_Ltk[Lr*512];
__device__ float g_lqp[Hh*Lr*DKq];
__device__ float g_lkp[Hh*Lr*DKq];
__device__ float g_c2p [(size_t)Bq*Hh*Nq*Lr];
__device__ float g_p2cT[(size_t)Bq*Hh*Nq*Lr];
__device__ float g_S   [(size_t)Bq*Hh*Nq*Nq];    // c2c scores (pre-scaled)

#define NELT (Bq*Nq*Dq)
// bf16 hi/lo splits
__device__ __nv_bfloat16 s_qry_h[NELT], s_qry_l[NELT];
__device__ __nv_bfloat16 s_key_h[NELT], s_key_l[NELT];
__device__ __nv_bfloat16 s_val_h[NELT], s_val_l[NELT];
__device__ __nv_bfloat16 s_pq_h [NELT], s_pq_l [NELT];   // projected q (from GEMM epilogue)
__device__ __nv_bfloat16 s_pk_h [NELT], s_pk_l [NELT];   // projected k
__device__ __nv_bfloat16 s_att_h[NELT], s_att_l[NELT];   // attn out (from attn epilogue)
__device__ __nv_bfloat16 wtq_h[Dq*Dq], wtq_l[Dq*Dq];     // W^T [N][K]
__device__ __nv_bfloat16 wtk_h[Dq*Dq], wtk_l[Dq*Dq];
__device__ __nv_bfloat16 wtv_h[Dq*Dq], wtv_l[Dq*Dq];
__device__ __nv_bfloat16 wto_h[Dq*Dq], wto_l[Dq*Dq];
__device__ __nv_bfloat16 wtlq_h[512*Dq], wtlq_l[512*Dq];
__device__ __nv_bfloat16 wtlk_h[512*Dq], wtlk_l[512*Dq];
__device__ __nv_bfloat16 wttq_h[512*Dq], wttq_l[512*Dq];
__device__ __nv_bfloat16 wttk_h[512*Dq], wttk_l[512*Dq];
__device__ __nv_bfloat16 s_l_h[Lr*Dq], s_l_l[Lr*Dq];
__device__ __nv_bfloat16 s_t_h[Lr*Dq], s_t_l[Lr*Dq];
__device__ __nv_bfloat16 s_lqp_h[Hh*Lr*DKq], s_lqp_l[Hh*Lr*DKq];
__device__ __nv_bfloat16 s_lkp_h[Hh*Lr*DKq], s_lkp_l[Hh*Lr*DKq];

// ==================== elementwise fp32 -> bf16 hi/lo ========================
__global__ void split_f32(const float* __restrict__ src,
                          __nv_bfloat16* __restrict__ hi, __nv_bfloat16* __restrict__ lo)
{
    int i = (blockIdx.x * blockDim.x + threadIdx.x) * 4;
    float4 v = *(const float4*)(src + i);
    float x[4] = {v.x, v.y, v.z, v.w};
    __nv_bfloat16 h[4], l[4];
    #pragma unroll
    for (int t = 0; t < 4; t++) split1(x[t], h[t], l[t]);
    *(__nv_bfloat162*)(hi + i)     = __nv_bfloat162(h[0], h[1]);
    *(__nv_bfloat162*)(hi + i + 2) = __nv_bfloat162(h[2], h[3]);
    *(__nv_bfloat162*)(lo + i)     = __nv_bfloat162(l[0], l[1]);
    *(__nv_bfloat162*)(lo + i + 2) = __nv_bfloat162(l[2], l[3]);
}

// ============ transpose + split: W[K,N] fp32 -> Wt_hi/lo [N,K] bf16 =========
__global__ void tsplit(const float* __restrict__ W, int Kd, int Nd,
                       __nv_bfloat16* __restrict__ Th, __nv_bfloat16* __restrict__ Tl)
{
    __shared__ float t[32][33];
    int k0 = blockIdx.x * 32, n0 = blockIdx.y * 32;
    int tx = threadIdx.x, ty = threadIdx.y;            // 32 x 8
    for (int r = ty; r < 32; r += 8)
        t[r][tx] = W[(size_t)(k0 + r) * Nd + n0 + tx];
    __syncthreads();
    for (int r = ty; r < 32; r += 8) {
        float x = t[tx][r];                            // W[k0+tx][n0+r]
        __nv_bfloat16 h, l;
        split1(x, h, l);
        Th[(size_t)(n0 + r) * Kd + k0 + tx] = h;
        Tl[(size_t)(n0 + r) * Kd + k0 + tx] = l;
    }
}

// ============== warp-MMA bf16x3 GEMM: C = alpha*(A @ B^T) + bias ============
// A [M,K] (hi/lo, K-major, lda), B [N,K] (hi/lo, K-major, ldb), C [M,N] fp32.
// CTA tile 128x128, 8 warps x (64x32), m16n8k16, K-chunk 32, double-buffered
// cp.async, ldmatrix fragment loads.
// mode 0: plain. mode 1: A batched z=(b,h), B over h. mode 2: both.
// Optional Chi/Clo: bf16 hi/lo split of the result, same layout.
#define KC    32
#define SROW  40                      // padded row length (bf16) -> 80B stride
#define ABYT  (128 * SROW * 2)        // 10240 bytes per sub-array
#define STG   (4 * ABYT)              // 40960 per stage

__global__ __launch_bounds__(256)
void gemm_tc(const __nv_bfloat16* __restrict__ Ah_, const __nv_bfloat16* __restrict__ Al_,
             int lda, size_t aBatch,
             const __nv_bfloat16* __restrict__ Bh_, const __nv_bfloat16* __restrict__ Bl_,
             int ldb, size_t bBatch,
             float* __restrict__ C_, int ldc, size_t cBatch,
             __nv_bfloat16* __restrict__ Chi, __nv_bfloat16* __restrict__ Clo,
             const float* __restrict__ bias, float alpha, int K, int mode)
{
    extern __shared__ char dynsm[];
    const uint32_t smem_u = smem_to_u32(dynsm);
    const int tid = threadIdx.x;
    const int w = tid >> 5, lane = tid & 31;
    const int g = lane >> 2, tg = lane & 3;
    const int wm = w & 1, wn = w >> 1;                 // warp tile: 64x32

    // ldmatrix per-lane selectors
    // A x4 (m16k16): matrices (m0-7,k0-7)(m8-15,k0-7)(m0-7,k8-15)(m8-15,k8-15)
    const int aRow = (lane & 7) + ((lane >> 3) & 1) * 8;
    const int aCol = ((lane >> 4) & 1) * 16;
    // B x4 over ni-pair (n16k16): (n0-7,k0-7)(n0-7,k8-15)(n8-15,k0-7)(n8-15,k8-15)
    const int bRow = (lane & 7) + ((lane >> 4) & 1) * 8;
    const int bCol = ((lane >> 3) & 1) * 16;

    const __nv_bfloat16 *Ah = Ah_, *Al = Al_, *Bh = Bh_, *Bl = Bl_;
    float* C = C_;
    if (mode) {
        int z = blockIdx.z, b = z >> 3, h = z & 7;
        size_t ao = (size_t)b * aBatch + (size_t)h * 128;
        Ah += ao; Al += ao;
        if (mode == 1) { Bh += (size_t)h * bBatch; Bl += (size_t)h * bBatch; }
        else           { Bh += ao; Bl += ao; }
        C += (size_t)z * cBatch;
    }
    const int m0 = blockIdx.x * 128, n0 = blockIdx.y * 128;

    float acc[4][4][4] = {};                           // [mi][ni][c0..c3]

    const int nchunks = K / KC;

    // per-thread load slice: 2048 16B-copies per chunk, 8 per thread
    auto load_chunk = [&](int kc, int st) {
        const int k0 = kc * KC;
        uint32_t stbase = smem_u + st * STG;
        #pragma unroll
        for (int u = 0; u < 8; u++) {
            int it = tid + 256 * u;
            int arr = it >> 9, idx = it & 511;
            int row = idx >> 2, seg = idx & 3;
            uint32_t so = stbase + arr * ABYT + row * (SROW * 2) + seg * 16;
            const __nv_bfloat16* gp;
            if (arr == 0)      gp = Ah + (size_t)(m0 + row) * lda + k0 + seg * 8;
            else if (arr == 1) gp = Al + (size_t)(m0 + row) * lda + k0 + seg * 8;
            else if (arr == 2) gp = Bh + (size_t)(n0 + row) * ldb + k0 + seg * 8;
            else               gp = Bl + (size_t)(n0 + row) * ldb + k0 + seg * 8;
            CP_ASYNC_16(so, gp);
        }
        CP_ASYNC_COMMIT();
    };

    load_chunk(0, 0);
    for (int kc = 0; kc < nchunks; kc++) {
        const int st = kc & 1;
        bool more = (kc + 1 < nchunks);
        if (more) load_chunk(kc + 1, st ^ 1);
        if (more) { CP_ASYNC_WAIT(1); } else { CP_ASYNC_WAIT(0); }
        __syncthreads();

        const uint32_t sbase = smem_u + st * STG;

        #pragma unroll
        for (int ks = 0; ks < KC / 16; ks++) {
            const int kb = ks * 32;                    // byte offset of k0 in a row
            uint32_t fAh[4][4], fAl[4][4], fBh[4][2], fBl[4][2];
            #pragma unroll
            for (int mi = 0; mi < 4; mi++) {
                uint32_t ra = sbase + (wm * 64 + mi * 16 + aRow) * (SROW * 2) + kb + aCol;
                ldsm4(fAh[mi], ra);
                ldsm4(fAl[mi], ra + ABYT);
            }
            #pragma unroll
            for (int np = 0; np < 2; np++) {
                uint32_t rb = sbase + 2 * ABYT
                            + (wn * 32 + np * 16 + bRow) * (SROW * 2) + kb + bCol;
                uint32_t t[4];
                ldsm4(t, rb);
                fBh[2*np][0] = t[0]; fBh[2*np][1] = t[1];
                fBh[2*np+1][0] = t[2]; fBh[2*np+1][1] = t[3];
                ldsm4(t, rb + ABYT);
                fBl[2*np][0] = t[0]; fBl[2*np][1] = t[1];
                fBl[2*np+1][0] = t[2]; fBl[2*np+1][1] = t[3];
            }
            #pragma unroll
            for (int mi = 0; mi < 4; mi++)
                #pragma unroll
                for (int ni = 0; ni < 4; ni++) {
                    mma16816(acc[mi][ni], fAh[mi], fBh[ni]);
                    mma16816(acc[mi][ni], fAh[mi], fBl[ni]);
                    mma16816(acc[mi][ni], fAl[mi], fBh[ni]);
                }
        }
        __syncthreads();
    }

    // epilogue
    #pragma unroll
    for (int mi = 0; mi < 4; mi++) {
        int row0 = m0 + wm * 64 + mi * 16 + g;
        #pragma unroll
        for (int ni = 0; ni < 4; ni++) {
            int col = n0 + wn * 32 + ni * 8 + tg * 2;
            float b0 = bias ? bias[col] : 0.f;
            float b1 = bias ? bias[col + 1] : 0.f;
            float v00 = acc[mi][ni][0] * alpha + b0, v01 = acc[mi][ni][1] * alpha + b1;
            float v10 = acc[mi][ni][2] * alpha + b0, v11 = acc[mi][ni][3] * alpha + b1;
            if (C) {
                *(float2*)(C + (size_t)row0 * ldc + col)       = make_float2(v00, v01);
                *(float2*)(C + (size_t)(row0 + 8) * ldc + col) = make_float2(v10, v11);
            }
            if (Chi) {
                __nv_bfloat16 h00, l00, h01, l01, h10, l10, h11, l11;
                split1(v00, h00, l00); split1(v01, h01, l01);
                split1(v10, h10, l10); split1(v11, h11, l11);
                *(__nv_bfloat162*)(Chi + (size_t)row0 * ldc + col)       = __nv_bfloat162(h00, h01);
                *(__nv_bfloat162*)(Chi + (size_t)(row0 + 8) * ldc + col) = __nv_bfloat162(h10, h11);
                *(__nv_bfloat162*)(Clo + (size_t)row0 * ldc + col)       = __nv_bfloat162(l00, l01);
                *(__nv_bfloat162*)(Clo + (size_t)(row0 + 8) * ldc + col) = __nv_bfloat162(l10, l11);
            }
        }
    }
}

// ---- pack concat heads: out[h][r][d] = (h<4 ? Ll : Lt)[r][ (h%4)*128 + d ] --
__global__ void pack_rel(const float* __restrict__ Ll, const float* __restrict__ Lt,
                         float* __restrict__ out)
{
    int idx = blockIdx.x * blockDim.x + threadIdx.x;
    int d = idx & 127;
    int r = (idx >> 7) & 511;
    int h = idx >> 16;
    const float* src = (h < 4) ? Ll : Lt;
    out[idx] = src[r * 512 + (h & 3) * 128 + d];
}

// ------------- fused gathers + mask + softmax + AV (c2c precomputed) --------
// CTA = (b,h) x 32 query rows; 8 warps, each warp 4 rows; lane = j within tile.
// Output written directly as bf16 hi/lo split (consumed by the Wo GEMM).
__global__ __launch_bounds__(256, 2)
void attn_fused(const int* __restrict__ rel, const int* __restrict__ mask)
{
    extern __shared__ char dynsm[];
    float* c2ps = (float*)dynsm;          // [32][512]
    float* vs   = c2ps + 32 * 512;        // [32][128]

    const int bh = blockIdx.y;
    const int b = bh >> 3, h = bh & 7;
    const int i0 = blockIdx.x * 32;
    const int tid = threadIdx.x;
    const int w  = tid >> 5;
    const int jj = tid & 31;
    const int r0 = w * 4;

    for (int e = tid * 4; e < 32 * 512; e += 1024)
        *(float4*)&c2ps[e] =
            *(const float4*)(g_c2p + ((size_t)bh * Nq + i0 + (e >> 9)) * Lr + (e & 511));

    float m[4] = {-INFINITY, -INFINITY, -INFINITY, -INFINITY};
    float l[4] = {0.f, 0.f, 0.f, 0.f};
    float4 acc[4] = {};

    const float* Sb   = g_S + (size_t)bh * Nq * Nq;
    const int* relbh  = rel + (size_t)bh * Nq * Nq;
    const int* maskb  = mask + (size_t)b * Nq * Nq;
    const float* p2cb = g_p2cT + (size_t)bh * Nq * Lr;

    for (int j0 = 0; j0 < Nq; j0 += 32) {
        __syncthreads();
        #pragma unroll
        for (int t = 0; t < 4; t++) {
            int e = (tid + t * 256) * 4;
            int r = e >> 7, d = e & 127;
            *(float4*)&vs[e] =
                *(const float4*)(g_v + (size_t)(b * Nq + j0 + r) * Dq + h * DKq + d);
        }
        __syncthreads();

        const int j = j0 + jj;
        int4 r2v = *(const int4*)(relbh + (size_t)j * Nq + i0 + r0);
        const int* r2a = (const int*)&r2v;
        float s[4];
        #pragma unroll
        for (int r = 0; r < 4; r++) {
            int i = i0 + r0 + r;
            float sc = __ldg(Sb + (size_t)i * Nq + j);
            int r1 = __ldg(relbh + (size_t)i * Nq + j);
            sc += c2ps[(r0 + r) * 512 + r1];
            sc += __ldg(p2cb + (size_t)j * Lr + r2a[r]);
            if (__ldg(maskb + (size_t)i * Nq + j) == 1) sc = -1e9f;
            s[r] = sc;
        }
        float p[4];
        #pragma unroll
        for (int r = 0; r < 4; r++) {
            float t = s[r];
            #pragma unroll
            for (int o = 16; o; o >>= 1) t = fmaxf(t, __shfl_xor_sync(0xffffffffu, t, o));
            float mn = fmaxf(m[r], t);
            p[r] = __expf(s[r] - mn);
            float corr = __expf(m[r] - mn);
            float ps = p[r];
            #pragma unroll
            for (int o = 16; o; o >>= 1) ps += __shfl_xor_sync(0xffffffffu, ps, o);
            l[r] = l[r] * corr + ps;
            m[r] = mn;
            acc[r].x *= corr; acc[r].y *= corr; acc[r].z *= corr; acc[r].w *= corr;
        }
        #pragma unroll
        for (int t2 = 0; t2 < 32; t2++) {
            float4 vr = *(float4*)&vs[t2 * 128 + jj * 4];
            #pragma unroll
            for (int r = 0; r < 4; r++) {
                float pj = __shfl_sync(0xffffffffu, p[r], t2);
                acc[r].x += pj * vr.x; acc[r].y += pj * vr.y;
                acc[r].z += pj * vr.z; acc[r].w += pj * vr.w;
            }
        }
    }
    #pragma unroll
    for (int r = 0; r < 4; r++) {
        float inv = 1.f / l[r];
        float o[4] = {acc[r].x * inv, acc[r].y * inv, acc[r].z * inv, acc[r].w * inv};
        __nv_bfloat16 hh[4], ll[4];
        #pragma unroll
        for (int t = 0; t < 4; t++) split1(o[t], hh[t], ll[t]);
        size_t base = ((size_t)(b * Nq + i0 + r0 + r) * Hh + h) * DKq + jj * 4;
        *(__nv_bfloat162*)(s_att_h + base)     = __nv_bfloat162(hh[0], hh[1]);
        *(__nv_bfloat162*)(s_att_h + base + 2) = __nv_bfloat162(hh[2], hh[3]);
        *(__nv_bfloat162*)(s_att_l + base)     = __nv_bfloat162(ll[0], ll[1]);
        *(__nv_bfloat162*)(s_att_l + base + 2) = __nv_bfloat162(ll[2], ll[3]);
    }
}

// ---------------------------------------------------------------------------
#define GSA(p, sym) cudaGetSymbolAddress((void**)&p, sym)

extern "C" void kernel_launch(void* const* d_in, const int* in_sizes, int n_in,
                              void* d_out, int out_size)
{
    const float* query   = (const float*)d_in[0];
    const float* key     = (const float*)d_in[1];
    const float* value   = (const float*)d_in[2];
    const float* rel_emb = (const float*)d_in[3];
    const int*   rel     = (const int*)  d_in[4];
    const int*   mask    = (const int*)  d_in[5];
    const float* Wq  = (const float*)d_in[6];  const float* bq  = (const float*)d_in[7];
    const float* Wk  = (const float*)d_in[8];  const float* bk  = (const float*)d_in[9];
    const float* Wv  = (const float*)d_in[10]; const float* bv  = (const float*)d_in[11];
    const float* Wo  = (const float*)d_in[12]; const float* bo  = (const float*)d_in[13];
    const float* Wlq = (const float*)d_in[14]; const float* blq = (const float*)d_in[15];
    const float* Wlk = (const float*)d_in[16]; const float* blk = (const float*)d_in[17];
    const float* Wtq = (const float*)d_in[18]; const float* btq = (const float*)d_in[19];
    const float* Wtk = (const float*)d_in[20]; const float* btk = (const float*)d_in[21];
    float* out = (float*)d_out;

    float *p_v, *p_Llq, *p_Ltq, *p_Llk, *p_Ltk, *p_lqp, *p_lkp;
    float *p_c2p, *p_p2cT, *p_S;
    GSA(p_v, g_v);
    GSA(p_Llq, g_Llq); GSA(p_Ltq, g_Ltq); GSA(p_Llk, g_Llk); GSA(p_Ltk, g_Ltk);
    GSA(p_lqp, g_lqp); GSA(p_lkp, g_lkp); GSA(p_c2p, g_c2p); GSA(p_p2cT, g_p2cT);
    GSA(p_S, g_S);

    __nv_bfloat16 *qry_h,*qry_l,*key_h,*key_l,*val_h,*val_l,*pq_h,*pq_l,*pk_h,*pk_l,*att_h,*att_l;
    __nv_bfloat16 *wq_h,*wq_l,*wk_h,*wk_l,*wv_h,*wv_l,*wo_h,*wo_l;
    __nv_bfloat16 *wlq_h,*wlq_l,*wlk_h,*wlk_l,*wtq_hh,*wtq_ll,*wtk_hh,*wtk_ll;
    __nv_bfloat16 *l_h,*l_l,*t_h,*t_l,*lqp_h,*lqp_l,*lkp_h,*lkp_l;
    GSA(qry_h, s_qry_h); GSA(qry_l, s_qry_l);
    GSA(key_h, s_key_h); GSA(key_l, s_key_l);
    GSA(val_h, s_val_h); GSA(val_l, s_val_l);
    GSA(pq_h, s_pq_h); GSA(pq_l, s_pq_l);
    GSA(pk_h, s_pk_h); GSA(pk_l, s_pk_l);
    GSA(att_h, s_att_h); GSA(att_l, s_att_l);
    GSA(wq_h, wtq_h); GSA(wq_l, wtq_l); GSA(wk_h, wtk_h); GSA(wk_l, wtk_l);
    GSA(wv_h, wtv_h); GSA(wv_l, wtv_l); GSA(wo_h, wto_h); GSA(wo_l, wto_l);
    GSA(wlq_h, wtlq_h); GSA(wlq_l, wtlq_l); GSA(wlk_h, wtlk_h); GSA(wlk_l, wtlk_l);
    GSA(wtq_hh, wttq_h); GSA(wtq_ll, wttq_l); GSA(wtk_hh, wttk_h); GSA(wtk_ll, wttk_l);
    GSA(l_h, s_l_h); GSA(l_l, s_l_l); GSA(t_h, s_t_h); GSA(t_l, s_t_l);
    GSA(lqp_h, s_lqp_h); GSA(lqp_l, s_lqp_l); GSA(lkp_h, s_lkp_h); GSA(lkp_l, s_lkp_l);

    const float* lmat = rel_emb;
    const float* tmat = rel_emb + Lr * Dq;

    const int GEMM_SMEM = 2 * STG;                          // 81920 B
    cudaFuncSetAttribute(gemm_tc, cudaFuncAttributeMaxDynamicSharedMemorySize, GEMM_SMEM);
    const int ATTN_SMEM = (32 * 512 + 32 * 128) * 4;        // 80 KB
    cudaFuncSetAttribute(attn_fused, cudaFuncAttributeMaxDynamicSharedMemorySize, ATTN_SMEM);

    // 0) weight transpose+split; activation splits
    {
        dim3 t32(32, 8);
        tsplit<<<dim3(32, 32), t32>>>(Wq, Dq, Dq, wq_h, wq_l);
        tsplit<<<dim3(32, 32), t32>>>(Wk, Dq, Dq, wk_h, wk_l);
        tsplit<<<dim3(32, 32), t32>>>(Wv, Dq, Dq, wv_h, wv_l);
        tsplit<<<dim3(32, 32), t32>>>(Wo, Dq, Dq, wo_h, wo_l);
        tsplit<<<dim3(32, 16), t32>>>(Wlq, Dq, 512, wlq_h, wlq_l);
        tsplit<<<dim3(32, 16), t32>>>(Wlk, Dq, 512, wlk_h, wlk_l);
        tsplit<<<dim3(32, 16), t32>>>(Wtq, Dq, 512, wtq_hh, wtq_ll);
        tsplit<<<dim3(32, 16), t32>>>(Wtk, Dq, 512, wtk_hh, wtk_ll);
        split_f32<<<NELT / 1024, 256>>>(query, qry_h, qry_l);
        split_f32<<<NELT / 1024, 256>>>(key,   key_h, key_l);
        split_f32<<<NELT / 1024, 256>>>(value, val_h, val_l);
        split_f32<<<(Lr * Dq) / 1024, 256>>>(lmat, l_h, l_l);
        split_f32<<<(Lr * Dq) / 1024, 256>>>(tmat, t_h, t_l);
    }

    // 1) q/k/v projections  [4096,1024]@[1024,1024]+b
    //    q/k: write bf16 hi/lo splits directly (fp32 never materialized)
    gemm_tc<<<dim3(32, 8, 1), 256, GEMM_SMEM>>>(qry_h, qry_l, Dq, 0, wq_h, wq_l, Dq, 0,
                                                nullptr, Dq, 0, pq_h, pq_l, bq, 1.f, Dq, 0);
    gemm_tc<<<dim3(32, 8, 1), 256, GEMM_SMEM>>>(key_h, key_l, Dq, 0, wk_h, wk_l, Dq, 0,
                                                nullptr, Dq, 0, pk_h, pk_l, bk, 1.f, Dq, 0);
    gemm_tc<<<dim3(32, 8, 1), 256, GEMM_SMEM>>>(val_h, val_l, Dq, 0, wv_h, wv_l, Dq, 0,
                                                p_v, Dq, 0, nullptr, nullptr, bv, 1.f, Dq, 0);

    // 2) rel projections [512,1024]@[1024,512]+b
    gemm_tc<<<dim3(4, 4, 1), 256, GEMM_SMEM>>>(l_h, l_l, Dq, 0, wlq_h, wlq_l, Dq, 0,
                                               p_Llq, 512, 0, nullptr, nullptr, blq, 1.f, Dq, 0);
    gemm_tc<<<dim3(4, 4, 1), 256, GEMM_SMEM>>>(l_h, l_l, Dq, 0, wlk_h, wlk_l, Dq, 0,
                                               p_Llk, 512, 0, nullptr, nullptr, blk, 1.f, Dq, 0);
    gemm_tc<<<dim3(4, 4, 1), 256, GEMM_SMEM>>>(t_h, t_l, Dq, 0, wtq_hh, wtq_ll, Dq, 0,
                                               p_Ltq, 512, 0, nullptr, nullptr, btq, 1.f, Dq, 0);
    gemm_tc<<<dim3(4, 4, 1), 256, GEMM_SMEM>>>(t_h, t_l, Dq, 0, wtk_hh, wtk_ll, Dq, 0,
                                               p_Ltk, 512, 0, nullptr, nullptr, btk, 1.f, Dq, 0);

    // 3) pack + splits (rel tables only)
    pack_rel<<<(Hh * Lr * DKq) / 256, 256>>>(p_Llq, p_Ltq, p_lqp);
    pack_rel<<<(Hh * Lr * DKq) / 256, 256>>>(p_Llk, p_Ltk, p_lkp);
    split_f32<<<(Hh * Lr * DKq) / 1024, 256>>>(p_lqp, lqp_h, lqp_l);
    split_f32<<<(Hh * Lr * DKq) / 1024, 256>>>(p_lkp, lkp_h, lkp_l);

    // 4) c2p_full[b,h,i,r]=(q_i.lk_r)/scale ; p2cT[b,h,j,r]=(k_j.lq_r)/scale
    gemm_tc<<<dim3(8, 4, 32), 256, GEMM_SMEM>>>(pq_h, pq_l, Dq, (size_t)Nq * Dq,
                                                lkp_h, lkp_l, DKq, (size_t)Lr * DKq,
                                                p_c2p, Lr, (size_t)Nq * Lr,
                                                nullptr, nullptr, nullptr, INV_SCALE, DKq, 1);
    gemm_tc<<<dim3(8, 4, 32), 256, GEMM_SMEM>>>(pk_h, pk_l, Dq, (size_t)Nq * Dq,
                                                lqp_h, lqp_l, DKq, (size_t)Lr * DKq,
                                                p_p2cT, Lr, (size_t)Nq * Lr,
                                                nullptr, nullptr, nullptr, INV_SCALE, DKq, 1);

    // 5) c2c scores: S[b,h,i,j] = (q_i.k_j)/scale   (batched over (b,h))
    gemm_tc<<<dim3(8, 8, 32), 256, GEMM_SMEM>>>(pq_h, pq_l, Dq, (size_t)Nq * Dq,
                                                pk_h, pk_l, Dq, 0,
                                                p_S, Nq, (size_t)Nq * Nq,
                                                nullptr, nullptr, nullptr, INV_SCALE, DKq, 2);

    // 6) fused attention (gathers + softmax + AV) -> writes att hi/lo splits
    attn_fused<<<dim3(Nq / 32, Bq * Hh), 256, ATTN_SMEM>>>(rel, mask);

    // 7) output projection
    gemm_tc<<<dim3(32, 8, 1), 256, GEMM_SMEM>>>(att_h, att_l, Dq, 0, wo_h, wo_l, Dq, 0,
                                                out, Dq, 0, nullptr, nullptr, bo, 1.f, Dq, 0);
}

// round 16
// speedup vs baseline: 1.1113x; 1.0261x over previous
#include <cuda_runtime.h>
#include <cuda_bf16.h>
#include <math.h>
#include <stdint.h>

// Problem constants
#define Bq   4
#define Nq   1024
#define Dq   1024
#define Hh   8
#define Lr   512
#define DKq  128

#define INV_SCALE 0.051031036307982884f  // 1/sqrt(128*3)

// ======================= portable PTX helpers ===============================
__device__ __forceinline__ uint32_t smem_to_u32(const void* p) {
    uint32_t a;
    asm("{ .reg .u64 t; cvta.to.shared.u64 t, %1; cvt.u32.u64 %0, t; }" : "=r"(a) : "l"(p));
    return a;
}
#define CP_ASYNC_16(dst_u32, src_ptr) \
    asm volatile("cp.async.cg.shared.global [%0], [%1], 16;" :: "r"(dst_u32), "l"(src_ptr))
#define CP_ASYNC_COMMIT() asm volatile("cp.async.commit_group;" ::: "memory")
#define CP_ASYNC_WAIT(n)  asm volatile("cp.async.wait_group %0;" :: "n"(n) : "memory")

// m16n8k16 bf16 MMA, fp32 accum (portable sm_80+ PTX -> HMMA on Blackwell)
__device__ __forceinline__ void mma16816(float* c, const uint32_t* a, const uint32_t* b) {
    asm volatile(
        "mma.sync.aligned.m16n8k16.row.col.f32.bf16.bf16.f32 "
        "{%0,%1,%2,%3}, {%4,%5,%6,%7}, {%8,%9}, {%0,%1,%2,%3};"
        : "+f"(c[0]), "+f"(c[1]), "+f"(c[2]), "+f"(c[3])
        : "r"(a[0]), "r"(a[1]), "r"(a[2]), "r"(a[3]), "r"(b[0]), "r"(b[1]));
}

// ldmatrix x4: loads 4 8x8 b16 matrices; lane i of each 8-lane group supplies a row addr
__device__ __forceinline__ void ldsm4(uint32_t* r, uint32_t a) {
    asm volatile("ldmatrix.sync.aligned.m8n8.x4.shared.b16 {%0,%1,%2,%3}, [%4];"
        : "=r"(r[0]), "=r"(r[1]), "=r"(r[2]), "=r"(r[3]) : "r"(a));
}

__device__ __forceinline__ void split1(float x, __nv_bfloat16& h, __nv_bfloat16& l) {
    h = __float2bfloat16(x);
    l = __float2bfloat16(x - __bfloat162float(h));
}

// ================== scratch (device globals; no allocs) =====================
__device__ float g_v  [Bq*Nq*Dq];
__device__ float g_Llq[Lr*512];
__device__ float g_Ltq[Lr*512];
__device__ float g_Llk[Lr*512];
__device__ float g_Ltk[Lr*512];
__device__ float g_c2p [(size_t)Bq*Hh*Nq*Lr];
__device__ float g_p2cT[(size_t)Bq*Hh*Nq*Lr];
__device__ float g_S   [(size_t)Bq*Hh*Nq*Nq];    // c2c scores (pre-scaled)

#define NELT (Bq*Nq*Dq)
// bf16 hi/lo splits
__device__ __nv_bfloat16 s_qry_h[NELT], s_qry_l[NELT];
__device__ __nv_bfloat16 s_key_h[NELT], s_key_l[NELT];
__device__ __nv_bfloat16 s_val_h[NELT], s_val_l[NELT];
__device__ __nv_bfloat16 s_pq_h [NELT], s_pq_l [NELT];   // projected q (from GEMM epilogue)
__device__ __nv_bfloat16 s_pk_h [NELT], s_pk_l [NELT];   // projected k
__device__ __nv_bfloat16 s_att_h[NELT], s_att_l[NELT];   // attn out (from attn epilogue)
__device__ __nv_bfloat16 wtq_h[Dq*Dq], wtq_l[Dq*Dq];     // W^T [N][K]
__device__ __nv_bfloat16 wtk_h[Dq*Dq], wtk_l[Dq*Dq];
__device__ __nv_bfloat16 wtv_h[Dq*Dq], wtv_l[Dq*Dq];
__device__ __nv_bfloat16 wto_h[Dq*Dq], wto_l[Dq*Dq];
__device__ __nv_bfloat16 wtlq_h[512*Dq], wtlq_l[512*Dq];
__device__ __nv_bfloat16 wtlk_h[512*Dq], wtlk_l[512*Dq];
__device__ __nv_bfloat16 wttq_h[512*Dq], wttq_l[512*Dq];
__device__ __nv_bfloat16 wttk_h[512*Dq], wttk_l[512*Dq];
__device__ __nv_bfloat16 s_l_h[Lr*Dq], s_l_l[Lr*Dq];
__device__ __nv_bfloat16 s_t_h[Lr*Dq], s_t_l[Lr*Dq];
__device__ __nv_bfloat16 s_lqp_h[Hh*Lr*DKq], s_lqp_l[Hh*Lr*DKq];
__device__ __nv_bfloat16 s_lkp_h[Hh*Lr*DKq], s_lkp_l[Hh*Lr*DKq];

// ==================== elementwise fp32 -> bf16 hi/lo ========================
__global__ void split_f32(const float* __restrict__ src,
                          __nv_bfloat16* __restrict__ hi, __nv_bfloat16* __restrict__ lo)
{
    int i = (blockIdx.x * blockDim.x + threadIdx.x) * 4;
    float4 v = *(const float4*)(src + i);
    float x[4] = {v.x, v.y, v.z, v.w};
    __nv_bfloat16 h[4], l[4];
    #pragma unroll
    for (int t = 0; t < 4; t++) split1(x[t], h[t], l[t]);
    *(__nv_bfloat162*)(hi + i)     = __nv_bfloat162(h[0], h[1]);
    *(__nv_bfloat162*)(hi + i + 2) = __nv_bfloat162(h[2], h[3]);
    *(__nv_bfloat162*)(lo + i)     = __nv_bfloat162(l[0], l[1]);
    *(__nv_bfloat162*)(lo + i + 2) = __nv_bfloat162(l[2], l[3]);
}

// ============ transpose + split: W[K,N] fp32 -> Wt_hi/lo [N,K] bf16 =========
__global__ void tsplit(const float* __restrict__ W, int Kd, int Nd,
                       __nv_bfloat16* __restrict__ Th, __nv_bfloat16* __restrict__ Tl)
{
    __shared__ float t[32][33];
    int k0 = blockIdx.x * 32, n0 = blockIdx.y * 32;
    int tx = threadIdx.x, ty = threadIdx.y;            // 32 x 8
    for (int r = ty; r < 32; r += 8)
        t[r][tx] = W[(size_t)(k0 + r) * Nd + n0 + tx];
    __syncthreads();
    for (int r = ty; r < 32; r += 8) {
        float x = t[tx][r];                            // W[k0+tx][n0+r]
        __nv_bfloat16 h, l;
        split1(x, h, l);
        Th[(size_t)(n0 + r) * Kd + k0 + tx] = h;
        Tl[(size_t)(n0 + r) * Kd + k0 + tx] = l;
    }
}

// -- pack concat heads + split: out[h][r][d] = (h<4?Ll:Lt)[r][(h&3)*128+d] ---
__global__ void pack_split(const float* __restrict__ Ll, const float* __restrict__ Lt,
                           __nv_bfloat16* __restrict__ Oh, __nv_bfloat16* __restrict__ Ol)
{
    int idx = blockIdx.x * blockDim.x + threadIdx.x;   // H*L*DK = 524288
    int d = idx & 127;
    int r = (idx >> 7) & 511;
    int h = idx >> 16;
    const float* src = (h < 4) ? Ll : Lt;
    float x = src[r * 512 + (h & 3) * 128 + d];
    __nv_bfloat16 hh, ll;
    split1(x, hh, ll);
    Oh[idx] = hh;
    Ol[idx] = ll;
}

// ============== warp-MMA bf16x3 GEMM: C = alpha*(A @ B^T) + bias ============
// A [M,K] (hi/lo, K-major, lda), B [N,K] (hi/lo, K-major, ldb), C [M,N] fp32.
// CTA tile 128x128, 8 warps x (64x32), m16n8k16, K-chunk 32, double-buffered
// cp.async, ldmatrix fragment loads. Fragment buffers minimized (A reused for
// hi then lo) to hit 2 CTAs/SM.
// mode 0: plain. mode 1: A batched z=(b,h), B over h. mode 2: both.
// Optional Chi/Clo: bf16 hi/lo split of the result, same layout.
#define KC    32
#define SROW  40                      // padded row length (bf16) -> 80B stride
#define ABYT  (128 * SROW * 2)        // 10240 bytes per sub-array
#define STG   (4 * ABYT)              // 40960 per stage

__global__ __launch_bounds__(256, 2)
void gemm_tc(const __nv_bfloat16* __restrict__ Ah_, const __nv_bfloat16* __restrict__ Al_,
             int lda, size_t aBatch,
             const __nv_bfloat16* __restrict__ Bh_, const __nv_bfloat16* __restrict__ Bl_,
             int ldb, size_t bBatch,
             float* __restrict__ C_, int ldc, size_t cBatch,
             __nv_bfloat16* __restrict__ Chi, __nv_bfloat16* __restrict__ Clo,
             const float* __restrict__ bias, float alpha, int K, int mode)
{
    extern __shared__ char dynsm[];
    const uint32_t smem_u = smem_to_u32(dynsm);
    const int tid = threadIdx.x;
    const int w = tid >> 5, lane = tid & 31;
    const int g = lane >> 2, tg = lane & 3;
    const int wm = w & 1, wn = w >> 1;                 // warp tile: 64x32

    // ldmatrix per-lane selectors
    const int aRow = (lane & 7) + ((lane >> 3) & 1) * 8;
    const int aCol = ((lane >> 4) & 1) * 16;
    const int bRow = (lane & 7) + ((lane >> 4) & 1) * 8;
    const int bCol = ((lane >> 3) & 1) * 16;

    const __nv_bfloat16 *Ah = Ah_, *Al = Al_, *Bh = Bh_, *Bl = Bl_;
    float* C = C_;
    if (mode) {
        int z = blockIdx.z, b = z >> 3, h = z & 7;
        size_t ao = (size_t)b * aBatch + (size_t)h * 128;
        Ah += ao; Al += ao;
        if (mode == 1) { Bh += (size_t)h * bBatch; Bl += (size_t)h * bBatch; }
        else           { Bh += ao; Bl += ao; }
        C += (size_t)z * cBatch;
    }
    const int m0 = blockIdx.x * 128, n0 = blockIdx.y * 128;

    float acc[4][4][4] = {};                           // [mi][ni][c0..c3]

    const int nchunks = K / KC;

    auto load_chunk = [&](int kc, int st) {
        const int k0 = kc * KC;
        uint32_t stbase = smem_u + st * STG;
        #pragma unroll
        for (int u = 0; u < 8; u++) {
            int it = tid + 256 * u;
            int arr = it >> 9, idx = it & 511;
            int row = idx >> 2, seg = idx & 3;
            uint32_t so = stbase + arr * ABYT + row * (SROW * 2) + seg * 16;
            const __nv_bfloat16* gp;
            if (arr == 0)      gp = Ah + (size_t)(m0 + row) * lda + k0 + seg * 8;
            else if (arr == 1) gp = Al + (size_t)(m0 + row) * lda + k0 + seg * 8;
            else if (arr == 2) gp = Bh + (size_t)(n0 + row) * ldb + k0 + seg * 8;
            else               gp = Bl + (size_t)(n0 + row) * ldb + k0 + seg * 8;
            CP_ASYNC_16(so, gp);
        }
        CP_ASYNC_COMMIT();
    };

    load_chunk(0, 0);
    for (int kc = 0; kc < nchunks; kc++) {
        const int st = kc & 1;
        bool more = (kc + 1 < nchunks);
        if (more) load_chunk(kc + 1, st ^ 1);
        if (more) { CP_ASYNC_WAIT(1); } else { CP_ASYNC_WAIT(0); }
        __syncthreads();

        const uint32_t sbase = smem_u + st * STG;

        #pragma unroll
        for (int ks = 0; ks < KC / 16; ks++) {
            const int kb = ks * 32;                    // byte offset of k0 in a row
            uint32_t fA[4][4], fBh[4][2], fBl[4][2];
            // B-hi and B-lo fragments
            #pragma unroll
            for (int np = 0; np < 2; np++) {
                uint32_t rb = sbase + 2 * ABYT
                            + (wn * 32 + np * 16 + bRow) * (SROW * 2) + kb + bCol;
                uint32_t t[4];
                ldsm4(t, rb);
                fBh[2*np][0] = t[0]; fBh[2*np][1] = t[1];
                fBh[2*np+1][0] = t[2]; fBh[2*np+1][1] = t[3];
                ldsm4(t, rb + ABYT);
                fBl[2*np][0] = t[0]; fBl[2*np][1] = t[1];
                fBl[2*np+1][0] = t[2]; fBl[2*np+1][1] = t[3];
            }
            // A-hi: AhBh + AhBl
            #pragma unroll
            for (int mi = 0; mi < 4; mi++) {
                uint32_t ra = sbase + (wm * 64 + mi * 16 + aRow) * (SROW * 2) + kb + aCol;
                ldsm4(fA[mi], ra);
            }
            #pragma unroll
            for (int mi = 0; mi < 4; mi++)
                #pragma unroll
                for (int ni = 0; ni < 4; ni++) {
                    mma16816(acc[mi][ni], fA[mi], fBh[ni]);
                    mma16816(acc[mi][ni], fA[mi], fBl[ni]);
                }
            // A-lo (overwrites fA): AlBh
            #pragma unroll
            for (int mi = 0; mi < 4; mi++) {
                uint32_t ra = sbase + ABYT + (wm * 64 + mi * 16 + aRow) * (SROW * 2) + kb + aCol;
                ldsm4(fA[mi], ra);
            }
            #pragma unroll
            for (int mi = 0; mi < 4; mi++)
                #pragma unroll
                for (int ni = 0; ni < 4; ni++)
                    mma16816(acc[mi][ni], fA[mi], fBh[ni]);
        }
        __syncthreads();
    }

    // epilogue
    #pragma unroll
    for (int mi = 0; mi < 4; mi++) {
        int row0 = m0 + wm * 64 + mi * 16 + g;
        #pragma unroll
        for (int ni = 0; ni < 4; ni++) {
            int col = n0 + wn * 32 + ni * 8 + tg * 2;
            float b0 = bias ? bias[col] : 0.f;
            float b1 = bias ? bias[col + 1] : 0.f;
            float v00 = acc[mi][ni][0] * alpha + b0, v01 = acc[mi][ni][1] * alpha + b1;
            float v10 = acc[mi][ni][2] * alpha + b0, v11 = acc[mi][ni][3] * alpha + b1;
            if (C) {
                *(float2*)(C + (size_t)row0 * ldc + col)       = make_float2(v00, v01);
                *(float2*)(C + (size_t)(row0 + 8) * ldc + col) = make_float2(v10, v11);
            }
            if (Chi) {
                __nv_bfloat16 h00, l00, h01, l01, h10, l10, h11, l11;
                split1(v00, h00, l00); split1(v01, h01, l01);
                split1(v10, h10, l10); split1(v11, h11, l11);
                *(__nv_bfloat162*)(Chi + (size_t)row0 * ldc + col)       = __nv_bfloat162(h00, h01);
                *(__nv_bfloat162*)(Chi + (size_t)(row0 + 8) * ldc + col) = __nv_bfloat162(h10, h11);
                *(__nv_bfloat162*)(Clo + (size_t)row0 * ldc + col)       = __nv_bfloat162(l00, l01);
                *(__nv_bfloat162*)(Clo + (size_t)(row0 + 8) * ldc + col) = __nv_bfloat162(l10, l11);
            }
        }
    }
}

// ------------- fused gathers + mask + softmax + AV (c2c precomputed) --------
// CTA = (b,h) x 32 query rows; 8 warps, each warp 4 rows; lane = j within tile.
// Output written directly as bf16 hi/lo split (consumed by the Wo GEMM).
__global__ __launch_bounds__(256, 2)
void attn_fused(const int* __restrict__ rel, const int* __restrict__ mask)
{
    extern __shared__ char dynsm[];
    float* c2ps = (float*)dynsm;          // [32][512]
    float* vs   = c2ps + 32 * 512;        // [32][128]

    const int bh = blockIdx.y;
    const int b = bh >> 3, h = bh & 7;
    const int i0 = blockIdx.x * 32;
    const int tid = threadIdx.x;
    const int w  = tid >> 5;
    const int jj = tid & 31;
    const int r0 = w * 4;

    for (int e = tid * 4; e < 32 * 512; e += 1024)
        *(float4*)&c2ps[e] =
            *(const float4*)(g_c2p + ((size_t)bh * Nq + i0 + (e >> 9)) * Lr + (e & 511));

    float m[4] = {-INFINITY, -INFINITY, -INFINITY, -INFINITY};
    float l[4] = {0.f, 0.f, 0.f, 0.f};
    float4 acc[4] = {};

    const float* Sb   = g_S + (size_t)bh * Nq * Nq;
    const int* relbh  = rel + (size_t)bh * Nq * Nq;
    const int* maskb  = mask + (size_t)b * Nq * Nq;
    const float* p2cb = g_p2cT + (size_t)bh * Nq * Lr;

    for (int j0 = 0; j0 < Nq; j0 += 32) {
        __syncthreads();
        #pragma unroll
        for (int t = 0; t < 4; t++) {
            int e = (tid + t * 256) * 4;
            int r = e >> 7, d = e & 127;
            *(float4*)&vs[e] =
                *(const float4*)(g_v + (size_t)(b * Nq + j0 + r) * Dq + h * DKq + d);
        }
        __syncthreads();

        const int j = j0 + jj;
        int4 r2v = *(const int4*)(relbh + (size_t)j * Nq + i0 + r0);
        const int* r2a = (const int*)&r2v;
        float s[4];
        #pragma unroll
        for (int r = 0; r < 4; r++) {
            int i = i0 + r0 + r;
            float sc = __ldg(Sb + (size_t)i * Nq + j);
            int r1 = __ldg(relbh + (size_t)i * Nq + j);
            sc += c2ps[(r0 + r) * 512 + r1];
            sc += __ldg(p2cb + (size_t)j * Lr + r2a[r]);
            if (__ldg(maskb + (size_t)i * Nq + j) == 1) sc = -1e9f;
            s[r] = sc;
        }
        float p[4];
        #pragma unroll
        for (int r = 0; r < 4; r++) {
            float t = s[r];
            #pragma unroll
            for (int o = 16; o; o >>= 1) t = fmaxf(t, __shfl_xor_sync(0xffffffffu, t, o));
            float mn = fmaxf(m[r], t);
            p[r] = __expf(s[r] - mn);
            float corr = __expf(m[r] - mn);
            float ps = p[r];
            #pragma unroll
            for (int o = 16; o; o >>= 1) ps += __shfl_xor_sync(0xffffffffu, ps, o);
            l[r] = l[r] * corr + ps;
            m[r] = mn;
            acc[r].x *= corr; acc[r].y *= corr; acc[r].z *= corr; acc[r].w *= corr;
        }
        #pragma unroll
        for (int t2 = 0; t2 < 32; t2++) {
            float4 vr = *(float4*)&vs[t2 * 128 + jj * 4];
            #pragma unroll
            for (int r = 0; r < 4; r++) {
                float pj = __shfl_sync(0xffffffffu, p[r], t2);
                acc[r].x += pj * vr.x; acc[r].y += pj * vr.y;
                acc[r].z += pj * vr.z; acc[r].w += pj * vr.w;
            }
        }
    }
    #pragma unroll
    for (int r = 0; r < 4; r++) {
        float inv = 1.f / l[r];
        float o[4] = {acc[r].x * inv, acc[r].y * inv, acc[r].z * inv, acc[r].w * inv};
        __nv_bfloat16 hh[4], ll[4];
        #pragma unroll
        for (int t = 0; t < 4; t++) split1(o[t], hh[t], ll[t]);
        size_t base = ((size_t)(b * Nq + i0 + r0 + r) * Hh + h) * DKq + jj * 4;
        *(__nv_bfloat162*)(s_att_h + base)     = __nv_bfloat162(hh[0], hh[1]);
        *(__nv_bfloat162*)(s_att_h + base + 2) = __nv_bfloat162(hh[2], hh[3]);
        *(__nv_bfloat162*)(s_att_l + base)     = __nv_bfloat162(ll[0], ll[1]);
        *(__nv_bfloat162*)(s_att_l + base + 2) = __nv_bfloat162(ll[2], ll[3]);
    }
}

// ---------------------------------------------------------------------------
#define GSA(p, sym) cudaGetSymbolAddress((void**)&p, sym)

extern "C" void kernel_launch(void* const* d_in, const int* in_sizes, int n_in,
                              void* d_out, int out_size)
{
    const float* query   = (const float*)d_in[0];
    const float* key     = (const float*)d_in[1];
    const float* value   = (const float*)d_in[2];
    const float* rel_emb = (const float*)d_in[3];
    const int*   rel     = (const int*)  d_in[4];
    const int*   mask    = (const int*)  d_in[5];
    const float* Wq  = (const float*)d_in[6];  const float* bq  = (const float*)d_in[7];
    const float* Wk  = (const float*)d_in[8];  const float* bk  = (const float*)d_in[9];
    const float* Wv  = (const float*)d_in[10]; const float* bv  = (const float*)d_in[11];
    const float* Wo  = (const float*)d_in[12]; const float* bo  = (const float*)d_in[13];
    const float* Wlq = (const float*)d_in[14]; const float* blq = (const float*)d_in[15];
    const float* Wlk = (const float*)d_in[16]; const float* blk = (const float*)d_in[17];
    const float* Wtq = (const float*)d_in[18]; const float* btq = (const float*)d_in[19];
    const float* Wtk = (const float*)d_in[20]; const float* btk = (const float*)d_in[21];
    float* out = (float*)d_out;

    float *p_v, *p_Llq, *p_Ltq, *p_Llk, *p_Ltk, *p_c2p, *p_p2cT, *p_S;
    GSA(p_v, g_v);
    GSA(p_Llq, g_Llq); GSA(p_Ltq, g_Ltq); GSA(p_Llk, g_Llk); GSA(p_Ltk, g_Ltk);
    GSA(p_c2p, g_c2p); GSA(p_p2cT, g_p2cT); GSA(p_S, g_S);

    __nv_bfloat16 *qry_h,*qry_l,*key_h,*key_l,*val_h,*val_l,*pq_h,*pq_l,*pk_h,*pk_l,*att_h,*att_l;
    __nv_bfloat16 *wq_h,*wq_l,*wk_h,*wk_l,*wv_h,*wv_l,*wo_h,*wo_l;
    __nv_bfloat16 *wlq_h,*wlq_l,*wlk_h,*wlk_l,*wtq_hh,*wtq_ll,*wtk_hh,*wtk_ll;
    __nv_bfloat16 *l_h,*l_l,*t_h,*t_l,*lqp_h,*lqp_l,*lkp_h,*lkp_l;
    GSA(qry_h, s_qry_h); GSA(qry_l, s_qry_l);
    GSA(key_h, s_key_h); GSA(key_l, s_key_l);
    GSA(val_h, s_val_h); GSA(val_l, s_val_l);
    GSA(pq_h, s_pq_h); GSA(pq_l, s_pq_l);
    GSA(pk_h, s_pk_h); GSA(pk_l, s_pk_l);
    GSA(att_h, s_att_h); GSA(att_l, s_att_l);
    GSA(wq_h, wtq_h); GSA(wq_l, wtq_l); GSA(wk_h, wtk_h); GSA(wk_l, wtk_l);
    GSA(wv_h, wtv_h); GSA(wv_l, wtv_l); GSA(wo_h, wto_h); GSA(wo_l, wto_l);
    GSA(wlq_h, wtlq_h); GSA(wlq_l, wtlq_l); GSA(wlk_h, wtlk_h); GSA(wlk_l, wtlk_l);
    GSA(wtq_hh, wttq_h); GSA(wtq_ll, wttq_l); GSA(wtk_hh, wttk_h); GSA(wtk_ll, wttk_l);
    GSA(l_h, s_l_h); GSA(l_l, s_l_l); GSA(t_h, s_t_h); GSA(t_l, s_t_l);
    GSA(lqp_h, s_lqp_h); GSA(lqp_l, s_lqp_l); GSA(lkp_h, s_lkp_h); GSA(lkp_l, s_lkp_l);

    const float* lmat = rel_emb;
    const float* tmat = rel_emb + Lr * Dq;

    const int GEMM_SMEM = 2 * STG;                          // 81920 B
    cudaFuncSetAttribute(gemm_tc, cudaFuncAttributeMaxDynamicSharedMemorySize, GEMM_SMEM);
    const int ATTN_SMEM = (32 * 512 + 32 * 128) * 4;        // 80 KB
    cudaFuncSetAttribute(attn_fused, cudaFuncAttributeMaxDynamicSharedMemorySize, ATTN_SMEM);

    dim3 t32(32, 8);
    // Launch order chosen so launch index 5 (ncu -s 5 -c 1) is the Q-projection
    // gemm_tc. Deps for it: tsplit(Wq) [#0], split(query) [#1].
    tsplit<<<dim3(32, 32), t32>>>(Wq, Dq, Dq, wq_h, wq_l);               // #0
    split_f32<<<NELT / 1024, 256>>>(query, qry_h, qry_l);                // #1
    tsplit<<<dim3(32, 32), t32>>>(Wk, Dq, Dq, wk_h, wk_l);               // #2
    split_f32<<<NELT / 1024, 256>>>(key,   key_h, key_l);                // #3
    split_f32<<<NELT / 1024, 256>>>(value, val_h, val_l);                // #4
    // #5: Q projection (profiled by ncu)
    gemm_tc<<<dim3(32, 8, 1), 256, GEMM_SMEM>>>(qry_h, qry_l, Dq, 0, wq_h, wq_l, Dq, 0,
                                                nullptr, Dq, 0, pq_h, pq_l, bq, 1.f, Dq, 0);
    tsplit<<<dim3(32, 32), t32>>>(Wv, Dq, Dq, wv_h, wv_l);
    tsplit<<<dim3(32, 32), t32>>>(Wo, Dq, Dq, wo_h, wo_l);
    tsplit<<<dim3(32, 16), t32>>>(Wlq, Dq, 512, wlq_h, wlq_l);
    tsplit<<<dim3(32, 16), t32>>>(Wlk, Dq, 512, wlk_h, wlk_l);
    tsplit<<<dim3(32, 16), t32>>>(Wtq, Dq, 512, wtq_hh, wtq_ll);
    tsplit<<<dim3(32, 16), t32>>>(Wtk, Dq, 512, wtk_hh, wtk_ll);
    split_f32<<<(Lr * Dq) / 1024, 256>>>(lmat, l_h, l_l);
    split_f32<<<(Lr * Dq) / 1024, 256>>>(tmat, t_h, t_l);

    // K/V projections
    gemm_tc<<<dim3(32, 8, 1), 256, GEMM_SMEM>>>(key_h, key_l, Dq, 0, wk_h, wk_l, Dq, 0,
                                                nullptr, Dq, 0, pk_h, pk_l, bk, 1.f, Dq, 0);
    gemm_tc<<<dim3(32, 8, 1), 256, GEMM_SMEM>>>(val_h, val_l, Dq, 0, wv_h, wv_l, Dq, 0,
                                                p_v, Dq, 0, nullptr, nullptr, bv, 1.f, Dq, 0);

    // rel projections [512,1024]@[1024,512]+b  (fp32 out)
    gemm_tc<<<dim3(4, 4, 1), 256, GEMM_SMEM>>>(l_h, l_l, Dq, 0, wlq_h, wlq_l, Dq, 0,
                                               p_Llq, 512, 0, nullptr, nullptr, blq, 1.f, Dq, 0);
    gemm_tc<<<dim3(4, 4, 1), 256, GEMM_SMEM>>>(l_h, l_l, Dq, 0, wlk_h, wlk_l, Dq, 0,
                                               p_Llk, 512, 0, nullptr, nullptr, blk, 1.f, Dq, 0);
    gemm_tc<<<dim3(4, 4, 1), 256, GEMM_SMEM>>>(t_h, t_l, Dq, 0, wtq_hh, wtq_ll, Dq, 0,
                                               p_Ltq, 512, 0, nullptr, nullptr, btq, 1.f, Dq, 0);
    gemm_tc<<<dim3(4, 4, 1), 256, GEMM_SMEM>>>(t_h, t_l, Dq, 0, wtk_hh, wtk_ll, Dq, 0,
                                               p_Ltk, 512, 0, nullptr, nullptr, btk, 1.f, Dq, 0);

    // pack head-concat + split (fused; writes bf16 hi/lo directly)
    pack_split<<<(Hh * Lr * DKq) / 256, 256>>>(p_Llq, p_Ltq, lqp_h, lqp_l);
    pack_split<<<(Hh * Lr * DKq) / 256, 256>>>(p_Llk, p_Ltk, lkp_h, lkp_l);

    // c2p_full[b,h,i,r]=(q_i.lk_r)/scale ; p2cT[b,h,j,r]=(k_j.lq_r)/scale
    gemm_tc<<<dim3(8, 4, 32), 256, GEMM_SMEM>>>(pq_h, pq_l, Dq, (size_t)Nq * Dq,
                                                lkp_h, lkp_l, DKq, (size_t)Lr * DKq,
                                                p_c2p, Lr, (size_t)Nq * Lr,
                                                nullptr, nullptr, nullptr, INV_SCALE, DKq, 1);
    gemm_tc<<<dim3(8, 4, 32), 256, GEMM_SMEM>>>(pk_h, pk_l, Dq, (size_t)Nq * Dq,
                                                lqp_h, lqp_l, DKq, (size_t)Lr * DKq,
                                                p_p2cT, Lr, (size_t)Nq * Lr,
                                                nullptr, nullptr, nullptr, INV_SCALE, DKq, 1);

    // c2c scores: S[b,h,i,j] = (q_i.k_j)/scale   (batched over (b,h))
    gemm_tc<<<dim3(8, 8, 32), 256, GEMM_SMEM>>>(pq_h, pq_l, Dq, (size_t)Nq * Dq,
                                                pk_h, pk_l, Dq, 0,
                                                p_S, Nq, (size_t)Nq * Nq,
                                                nullptr, nullptr, nullptr, INV_SCALE, DKq, 2);

    // fused attention (gathers + softmax + AV) -> writes att hi/lo splits
    attn_fused<<<dim3(Nq / 32, Bq * Hh), 256, ATTN_SMEM>>>(rel, mask);

    // output projection
    gemm_tc<<<dim3(32, 8, 1), 256, GEMM_SMEM>>>(att_h, att_l, Dq, 0, wo_h, wo_l, Dq, 0,
                                                out, Dq, 0, nullptr, nullptr, bo, 1.f, Dq, 0);
}